// round 11
// baseline (speedup 1.0000x reference)
#include <cuda_runtime.h>

#define SEQ    1024
#define BATCH  2048
#define HID    64
#define G4     256
#define XCHUNK 256

typedef unsigned long long u64;

__device__ __forceinline__ u64 fma2(u64 a, u64 b, u64 c) {
    u64 d;
    asm("fma.rn.f32x2 %0, %1, %2, %3;" : "=l"(d) : "l"(a), "l"(b), "l"(c));
    return d;
}
__device__ __forceinline__ u64 add2(u64 a, u64 b) {
    u64 d;
    asm("add.rn.f32x2 %0, %1, %2;" : "=l"(d) : "l"(a), "l"(b));
    return d;
}
__device__ __forceinline__ u64 pack2(float a, float b) {
    u64 r;
    asm("mov.b64 %0, {%1, %2};" : "=l"(r) : "f"(a), "f"(b));
    return r;
}
__device__ __forceinline__ float2 unpack2(u64 v) {
    float2 f;
    asm("mov.b64 {%0, %1}, %2;" : "=f"(f.x), "=f"(f.y) : "l"(v));
    return f;
}
__device__ __forceinline__ float tanhA(float x) {
    float y;
    asm("tanh.approx.f32 %0, %1;" : "=f"(y) : "f"(x));
    return y;
}
__device__ __forceinline__ float sigA(float x) {
    return fmaf(0.5f, tanhA(0.5f * x), 0.5f);
}

// R10 (2 batches/CTA, weights-in-regs, smem gate exchange) + K-half split:
//   lane pair (2k, 2k+1) owns gate rows {p, p+128}, p = warp*16 + (lane>>1);
//   lane parity kh = lane&1 selects the 32-wide K-half each lane multiplies.
//   Per thread per 2-batch slot: 16 LDS.128 (was 32), 64 fma2 (same),
//   1 shfl_xor per batch to swap cross-partials, 1 activation per batch
//   (even lane finalizes row p, odd lane row p+128), 2 STS.
__global__ void __launch_bounds__(256, 2)
lstm_fused_kernel(const float* __restrict__ x,
                  const float* __restrict__ W_ih,
                  const float* __restrict__ W_hh,
                  const float* __restrict__ b_ih,
                  const float* __restrict__ b_hh,
                  const float* __restrict__ fc1_w,
                  const float* __restrict__ fc1_b,
                  const float* __restrict__ fc2_w,
                  const float* __restrict__ fc2_b,
                  float* __restrict__ out)
{
    const int b0   = blockIdx.x * 2;
    const int j    = threadIdx.x;
    const int lane = j & 31;
    const int wp   = j >> 5;
    const int p    = (wp << 4) + (lane >> 1);   // row-pair index 0..127
    const int kh   = lane & 1;                  // K-half 0/1
    const int rowP = p;                         // gates i/f region
    const int rowQ = p + 128;                   // gates g/o region
    const int rf   = kh ? rowQ : rowP;          // row this lane finalizes
    const bool isTanh = (kh == 1) && (p < 64);  // g-gate rows 128..191

    __shared__ __align__(16) float sh_hA[HID];
    __shared__ __align__(16) float sh_hB[HID];
    __shared__ float sh_g[2][G4];
    __shared__ float sh_x[2][XCHUNK];
    __shared__ float sh_c[2][HID];
    __shared__ float sh_hd[2][128];

    // ---- weights: rows {p, p+128}, K-half kh: 2 x 32 floats -> 32 u64 ----
    u64 wP[16], wQ[16];
    {
        const float4* pa = reinterpret_cast<const float4*>(W_hh + rowP * HID + kh * 32);
        const float4* pb = reinterpret_cast<const float4*>(W_hh + rowQ * HID + kh * 32);
        #pragma unroll
        for (int i = 0; i < 8; i++) {
            float4 va = __ldg(pa + i);
            float4 vb = __ldg(pb + i);
            wP[2 * i]     = pack2(va.x, va.y);
            wP[2 * i + 1] = pack2(va.z, va.w);
            wQ[2 * i]     = pack2(vb.x, vb.y);
            wQ[2 * i + 1] = pack2(vb.z, vb.w);
        }
    }
    const float wih  = __ldg(W_ih + rf);                      // finalized row only
    const float bias = __ldg(b_ih + rf) + __ldg(b_hh + rf);

    // ---- init ----
    if (j < HID) { sh_hA[j] = 0.0f; sh_hB[j] = 0.0f; }
    float c_reg = 0.0f;   // valid for j < 128 (unit = j&63, batch = j>>6)
    __syncthreads();

    // ---- time recurrence ----
    #pragma unroll 1
    for (int t0 = 0; t0 < SEQ; t0 += XCHUNK) {
        sh_x[0][j] = __ldg(x + (t0 + j) * BATCH + b0);
        sh_x[1][j] = __ldg(x + (t0 + j) * BATCH + b0 + 1);
        __syncthreads();

        #pragma unroll 1
        for (int tt = 0; tt < XCHUNK; tt++) {
            const float xv0 = sh_x[0][tt];
            const float xv1 = sh_x[1][tt];

            // this lane's 32-float K-half of both hidden states
            const ulonglong2* hA2 =
                reinterpret_cast<const ulonglong2*>(&sh_hA[kh * 32]);
            const ulonglong2* hB2 =
                reinterpret_cast<const ulonglong2*>(&sh_hB[kh * 32]);

            u64 aP0 = 0ull, aP1 = 0ull, aQ0 = 0ull, aQ1 = 0ull;  // batch 0
            u64 eP0 = 0ull, eP1 = 0ull, eQ0 = 0ull, eQ1 = 0ull;  // batch 1
            #pragma unroll
            for (int i = 0; i < 8; i++) {
                ulonglong2 ha = hA2[i];
                ulonglong2 hb = hB2[i];
                aP0 = fma2(ha.x, wP[2 * i],     aP0);
                aQ0 = fma2(ha.x, wQ[2 * i],     aQ0);
                eP0 = fma2(hb.x, wP[2 * i],     eP0);
                eQ0 = fma2(hb.x, wQ[2 * i],     eQ0);
                aP1 = fma2(ha.y, wP[2 * i + 1], aP1);
                aQ1 = fma2(ha.y, wQ[2 * i + 1], aQ1);
                eP1 = fma2(hb.y, wP[2 * i + 1], eP1);
                eQ1 = fma2(hb.y, wQ[2 * i + 1], eQ1);
            }
            float2 fP0 = unpack2(add2(aP0, aP1));
            float2 fQ0 = unpack2(add2(aQ0, aQ1));
            float2 fP1 = unpack2(add2(eP0, eP1));
            float2 fQ1 = unpack2(add2(eQ0, eQ1));
            const float vP0 = fP0.x + fP0.y;   // row p,     this K-half, batch 0
            const float vQ0 = fQ0.x + fQ0.y;   // row p+128, this K-half, batch 0
            const float vP1 = fP1.x + fP1.y;   // batch 1
            const float vQ1 = fQ1.x + fQ1.y;

            // cross-partial swap: even lane sends its row-q partial and
            // receives row-p's other half; odd lane vice-versa.
            const float own0  = kh ? vQ0 : vP0;
            const float send0 = kh ? vP0 : vQ0;
            const float own1  = kh ? vQ1 : vP1;
            const float send1 = kh ? vP1 : vQ1;
            const float recv0 = __shfl_xor_sync(0xffffffffu, send0, 1);
            const float recv1 = __shfl_xor_sync(0xffffffffu, send1, 1);

            const float pre0 = own0 + recv0 + fmaf(xv0, wih, bias);
            const float pre1 = own1 + recv1 + fmaf(xv1, wih, bias);

            sh_g[0][rf] = isTanh ? tanhA(pre0) : sigA(pre0);
            sh_g[1][rf] = isTanh ? tanhA(pre1) : sigA(pre1);
            __syncthreads();

            if (j < 128) {                 // 4 warps update both batches
                const int u  = j & 63;
                const int bt = j >> 6;
                const float iv = sh_g[bt][u];
                const float fv = sh_g[bt][u + 64];
                const float gv = sh_g[bt][u + 128];
                const float ov = sh_g[bt][u + 192];
                c_reg = fmaf(fv, c_reg, iv * gv);
                const float h = ov * tanhA(c_reg);
                if (bt == 0) sh_hA[u] = h; else sh_hB[u] = h;
            }
            __syncthreads();
        }
    }

    // ---- MLP head on both cell states ----
    if (j < 128) sh_c[j >> 6][j & 63] = c_reg;
    __syncthreads();

    {   // fc1: 256 threads = 2 batches x 128 rows
        const int bt  = j >> 7;
        const int row = j & 127;
        const float* fw = fc1_w + row * HID;
        float acc = __ldg(fc1_b + row);
        #pragma unroll
        for (int k = 0; k < HID; k++) acc = fmaf(__ldg(fw + k), sh_c[bt][k], acc);
        sh_hd[bt][row] = acc;
    }
    __syncthreads();

    if (j < 10) {        // fc2: 2 batches x 5 rows
        const int bt  = j / 5;
        const int row = j % 5;
        const float* fw = fc2_w + row * 128;
        float acc = __ldg(fc2_b + row);
        #pragma unroll
        for (int k = 0; k < 128; k++) acc = fmaf(__ldg(fw + k), sh_hd[bt][k], acc);
        out[(b0 + bt) * 5 + row] = acc;
    }
}

extern "C" void kernel_launch(void* const* d_in, const int* in_sizes, int n_in,
                              void* d_out, int out_size)
{
    const float* x     = (const float*)d_in[0];
    const float* W_ih  = (const float*)d_in[1];
    const float* W_hh  = (const float*)d_in[2];
    const float* b_ih  = (const float*)d_in[3];
    const float* b_hh  = (const float*)d_in[4];
    const float* fc1_w = (const float*)d_in[5];
    const float* fc1_b = (const float*)d_in[6];
    const float* fc2_w = (const float*)d_in[7];
    const float* fc2_b = (const float*)d_in[8];
    float* out = (float*)d_out;

    lstm_fused_kernel<<<BATCH / 2, 256>>>(x, W_ih, W_hh, b_ih, b_hh,
                                          fc1_w, fc1_b, fc2_w, fc2_b, out);
}

// round 12
// speedup vs baseline: 3.8701x; 3.8701x over previous
#include <cuda_runtime.h>

#define SEQ    1024
#define BATCH  2048
#define HID    64
#define NB     8        // batches per CTA
#define XCHUNK 128

__device__ __forceinline__ float tanhA(float x) {
    float y;
    asm("tanh.approx.f32 %0, %1;" : "=f"(y) : "f"(x));
    return y;
}
__device__ __forceinline__ float sigA(float x) {
    return fmaf(0.5f, tanhA(0.5f * x), 0.5f);
}
__device__ __forceinline__ unsigned cvt_tf32(float x) {
    unsigned r;
    asm("cvt.rna.tf32.f32 %0, %1;" : "=r"(r) : "f"(x));
    return r;
}
__device__ __forceinline__ void mma_tf32(float& d0, float& d1, float& d2, float& d3,
                                         unsigned a0, unsigned a1, unsigned a2, unsigned a3,
                                         unsigned b0, unsigned b1) {
    asm("mma.sync.aligned.m16n8k8.row.col.f32.tf32.tf32.f32 "
        "{%0,%1,%2,%3}, {%4,%5,%6,%7}, {%8,%9}, {%0,%1,%2,%3};"
        : "+f"(d0), "+f"(d1), "+f"(d2), "+f"(d3)
        : "r"(a0), "r"(a1), "r"(a2), "r"(a3), "r"(b0), "r"(b1));
}

// 8 batches/CTA via warp-level tf32 mma.sync:
//   D[256 rows, 8 batch] = W_hh[256,64] @ H[64,8] per step.
//   warp w owns rows 32w..32w+31 -> 2 m-tiles x 8 k-tiles of A fragments,
//   resident in 64 regs (tf32). Gate type of warp = w>>1 (uniform).
// Fragment maps (m16n8k8, gid = lane>>2, tig = lane&3):
//   A: a0=A[gid][tig] a1=A[gid+8][tig] a2=A[gid][tig+4] a3=A[gid+8][tig+4]
//   B: b0=B[tig][gid] b1=B[tig+4][gid]           (B = H k x n)
//   D: c0=D[gid][2tig] c1=D[gid][2tig+1] c2=D[gid+8][2tig] c3=D[gid+8][2tig+1]
// Per step: 16 LDS.32 B-frags, 16 mma, activations, gate STS, BAR,
//   update (256 threads x 2 (unit,batch) tasks, c in fp32 regs), BAR.
__global__ void __launch_bounds__(256, 2)
lstm_mma_kernel(const float* __restrict__ x,
                const float* __restrict__ W_ih,
                const float* __restrict__ W_hh,
                const float* __restrict__ b_ih,
                const float* __restrict__ b_hh,
                const float* __restrict__ fc1_w,
                const float* __restrict__ fc1_b,
                const float* __restrict__ fc2_w,
                const float* __restrict__ fc2_b,
                float* __restrict__ out)
{
    const int b0   = blockIdx.x * NB;
    const int j    = threadIdx.x;
    const int w    = j >> 5;
    const int lane = j & 31;
    const int gid  = lane >> 2;
    const int tig  = lane & 3;
    const int gk   = w >> 1;              // gate of this warp (0=i,1=f,2=g,3=o)
    const bool isG = (gk == 2);

    __shared__ float sh_H[HID * 10];      // H[k][n], pad 10 (tf32 bit patterns)
    __shared__ float sh_g[4 * 64 * 9];    // gates [gk][unit][batch], pad 9
    __shared__ float sh_x[XCHUNK * NB];   // x[tt][n]
    __shared__ float sh_c[NB][HID];
    __shared__ float sh_hd[NB][128];

    // ---- resident A fragments: W_hh rows 32w..32w+31, tf32 ----
    unsigned Afr[2][8][4];
    const int Rb0 = w * 32;
    #pragma unroll
    for (int mt = 0; mt < 2; mt++) {
        const int rA = Rb0 + mt * 16 + gid;
        #pragma unroll
        for (int kt = 0; kt < 8; kt++) {
            Afr[mt][kt][0] = cvt_tf32(__ldg(W_hh + rA * HID + kt * 8 + tig));
            Afr[mt][kt][1] = cvt_tf32(__ldg(W_hh + (rA + 8) * HID + kt * 8 + tig));
            Afr[mt][kt][2] = cvt_tf32(__ldg(W_hh + rA * HID + kt * 8 + tig + 4));
            Afr[mt][kt][3] = cvt_tf32(__ldg(W_hh + (rA + 8) * HID + kt * 8 + tig + 4));
        }
    }
    float wihA[2], wihB[2], biasA[2], biasB[2];
    #pragma unroll
    for (int mt = 0; mt < 2; mt++) {
        const int rA = Rb0 + mt * 16 + gid;
        const int rB = rA + 8;
        wihA[mt]  = __ldg(W_ih + rA);
        wihB[mt]  = __ldg(W_ih + rB);
        biasA[mt] = __ldg(b_ih + rA) + __ldg(b_hh + rA);
        biasB[mt] = __ldg(b_ih + rB) + __ldg(b_hh + rB);
    }

    // update-role constants: thread j handles unit uu, batches {2np, 2np+1}
    const int uu = j & 63;
    const int np = j >> 6;
    float c0r = 0.0f, c1r = 0.0f;

    // zero H
    for (int idx = j; idx < HID * 10; idx += 256) sh_H[idx] = 0.0f;
    __syncthreads();

    // ---- time recurrence ----
    #pragma unroll 1
    for (int t0 = 0; t0 < SEQ; t0 += XCHUNK) {
        #pragma unroll
        for (int i = 0; i < (XCHUNK * NB) / 256; i++) {
            const int idx = j + i * 256;
            const int tt  = idx >> 3;
            const int n   = idx & 7;
            sh_x[idx] = __ldg(x + (t0 + tt) * BATCH + b0 + n);
        }
        __syncthreads();

        #pragma unroll 1
        for (int tt = 0; tt < XCHUNK; tt++) {
            const float2 xv = *reinterpret_cast<const float2*>(&sh_x[tt * 8 + 2 * tig]);

            // init accumulators with x*W_ih + bias
            float d[2][4];
            #pragma unroll
            for (int mt = 0; mt < 2; mt++) {
                d[mt][0] = fmaf(xv.x, wihA[mt], biasA[mt]);
                d[mt][1] = fmaf(xv.y, wihA[mt], biasA[mt]);
                d[mt][2] = fmaf(xv.x, wihB[mt], biasB[mt]);
                d[mt][3] = fmaf(xv.y, wihB[mt], biasB[mt]);
            }

            // K loop: B fragments from smem H, 2 mma per k-tile
            #pragma unroll
            for (int kt = 0; kt < 8; kt++) {
                const unsigned bf0 = __float_as_uint(sh_H[(kt * 8 + tig) * 10 + gid]);
                const unsigned bf1 = __float_as_uint(sh_H[(kt * 8 + tig + 4) * 10 + gid]);
                mma_tf32(d[0][0], d[0][1], d[0][2], d[0][3],
                         Afr[0][kt][0], Afr[0][kt][1], Afr[0][kt][2], Afr[0][kt][3],
                         bf0, bf1);
                mma_tf32(d[1][0], d[1][1], d[1][2], d[1][3],
                         Afr[1][kt][0], Afr[1][kt][1], Afr[1][kt][2], Afr[1][kt][3],
                         bf0, bf1);
            }

            // activations + gate STS: rows -> units (unit = row & 63)
            #pragma unroll
            for (int mt = 0; mt < 2; mt++) {
                const int uA = (Rb0 + mt * 16 + gid) & 63;
                const int uB = uA + 8;
                const float g0 = isG ? tanhA(d[mt][0]) : sigA(d[mt][0]);
                const float g1 = isG ? tanhA(d[mt][1]) : sigA(d[mt][1]);
                const float g2 = isG ? tanhA(d[mt][2]) : sigA(d[mt][2]);
                const float g3 = isG ? tanhA(d[mt][3]) : sigA(d[mt][3]);
                sh_g[gk * 576 + uA * 9 + 2 * tig]     = g0;
                sh_g[gk * 576 + uA * 9 + 2 * tig + 1] = g1;
                sh_g[gk * 576 + uB * 9 + 2 * tig]     = g2;
                sh_g[gk * 576 + uB * 9 + 2 * tig + 1] = g3;
            }
            __syncthreads();

            // update: unit uu, batches 2np and 2np+1
            {
                const int o0 = uu * 9 + 2 * np;
                const float iv0 = sh_g[          o0];
                const float fv0 = sh_g[1 * 576 + o0];
                const float gv0 = sh_g[2 * 576 + o0];
                const float ov0 = sh_g[3 * 576 + o0];
                const float iv1 = sh_g[          o0 + 1];
                const float fv1 = sh_g[1 * 576 + o0 + 1];
                const float gv1 = sh_g[2 * 576 + o0 + 1];
                const float ov1 = sh_g[3 * 576 + o0 + 1];
                c0r = fmaf(fv0, c0r, iv0 * gv0);
                c1r = fmaf(fv1, c1r, iv1 * gv1);
                const float h0 = ov0 * tanhA(c0r);
                const float h1 = ov1 * tanhA(c1r);
                float2 hh;
                hh.x = __uint_as_float(cvt_tf32(h0));
                hh.y = __uint_as_float(cvt_tf32(h1));
                *reinterpret_cast<float2*>(&sh_H[uu * 10 + 2 * np]) = hh;
            }
            __syncthreads();
        }
    }

    // ---- MLP head on cell states (8 batches) ----
    sh_c[2 * np][uu]     = c0r;
    sh_c[2 * np + 1][uu] = c1r;
    __syncthreads();

    #pragma unroll
    for (int i = 0; i < 4; i++) {         // 8 batches x 128 rows = 1024 tasks
        const int t   = j + i * 256;
        const int row = t & 127;
        const int bt  = t >> 7;
        const float* fw = fc1_w + row * HID;
        float acc = __ldg(fc1_b + row);
        #pragma unroll
        for (int k = 0; k < HID; k++) acc = fmaf(__ldg(fw + k), sh_c[bt][k], acc);
        sh_hd[bt][row] = acc;
    }
    __syncthreads();

    if (j < NB * 5) {
        const int bt  = j / 5;
        const int row = j % 5;
        const float* fw = fc2_w + row * 128;
        float acc = __ldg(fc2_b + row);
        #pragma unroll
        for (int k = 0; k < 128; k++) acc = fmaf(__ldg(fw + k), sh_hd[bt][k], acc);
        out[(b0 + bt) * 5 + row] = acc;
    }
}

extern "C" void kernel_launch(void* const* d_in, const int* in_sizes, int n_in,
                              void* d_out, int out_size)
{
    const float* x     = (const float*)d_in[0];
    const float* W_ih  = (const float*)d_in[1];
    const float* W_hh  = (const float*)d_in[2];
    const float* b_ih  = (const float*)d_in[3];
    const float* b_hh  = (const float*)d_in[4];
    const float* fc1_w = (const float*)d_in[5];
    const float* fc1_b = (const float*)d_in[6];
    const float* fc2_w = (const float*)d_in[7];
    const float* fc2_b = (const float*)d_in[8];
    float* out = (float*)d_out;

    lstm_mma_kernel<<<BATCH / NB, 256>>>(x, W_ih, W_hh, b_ih, b_hh,
                                         fc1_w, fc1_b, fc2_w, fc2_b, out);
}

// round 13
// speedup vs baseline: 4.9756x; 1.2856x over previous
#include <cuda_runtime.h>

#define SEQ    1024
#define BATCH  2048
#define HID    64
#define NB     8        // batches per CTA
#define XCHUNK 128

__device__ __forceinline__ float tanhA(float x) {
    float y;
    asm("tanh.approx.f32 %0, %1;" : "=f"(y) : "f"(x));
    return y;
}
__device__ __forceinline__ float sigA(float x) {
    return fmaf(0.5f, tanhA(0.5f * x), 0.5f);
}
__device__ __forceinline__ unsigned cvt_tf32(float x) {
    unsigned r;
    asm("cvt.rna.tf32.f32 %0, %1;" : "=r"(r) : "f"(x));
    return r;
}
__device__ __forceinline__ void mma_tf32(float& d0, float& d1, float& d2, float& d3,
                                         unsigned a0, unsigned a1, unsigned a2, unsigned a3,
                                         unsigned b0, unsigned b1) {
    asm("mma.sync.aligned.m16n8k8.row.col.f32.tf32.tf32.f32 "
        "{%0,%1,%2,%3}, {%4,%5,%6,%7}, {%8,%9}, {%0,%1,%2,%3};"
        : "+f"(d0), "+f"(d1), "+f"(d2), "+f"(d3)
        : "r"(a0), "r"(a1), "r"(a2), "r"(a3), "r"(b0), "r"(b1));
}

// tf32 mma, gate-major row permutation so the LSTM update is register-local.
//
// Warp w's 32 logical rows (2 m-tiles of 16) are mapped to original W_hh rows:
//   m-tile mt, fragment row r in {gid, gid+8}:
//     mt=0: rows {gate0(i), gate1(f)} of unit u = w*8+gid
//     mt=1: rows {gate2(g), gate3(o)} of unit u
//   (original row of gate g, unit u  =  g*64 + u)
// D fragment (m16n8k8): thread(gid,tig) holds rows {gid,gid+8}, cols {2tig,2tig+1}
//   => after both m-tiles this thread owns i,f,g,o of unit u for batches
//      {2tig, 2tig+1}. Update in registers; c in-thread; h -> sh_H (STS.64).
// sh_H[64][8]: B-frag addr = 64*kt + 8*tig + gid -> conflict-free.
// ONE __syncthreads per step (double-buffered H).
__global__ void __launch_bounds__(256, 2)
lstm_mma_kernel(const float* __restrict__ x,
                const float* __restrict__ W_ih,
                const float* __restrict__ W_hh,
                const float* __restrict__ b_ih,
                const float* __restrict__ b_hh,
                const float* __restrict__ fc1_w,
                const float* __restrict__ fc1_b,
                const float* __restrict__ fc2_w,
                const float* __restrict__ fc2_b,
                float* __restrict__ out)
{
    const int b0   = blockIdx.x * NB;
    const int j    = threadIdx.x;
    const int w    = j >> 5;
    const int lane = j & 31;
    const int gid  = lane >> 2;
    const int tig  = lane & 3;
    const int u    = w * 8 + gid;          // hidden unit owned by this thread

    __shared__ float sh_H[2][HID][8];      // double-buffered H (tf32 bits), [k][n]
    __shared__ float sh_x[XCHUNK * NB];    // x[tt][n]
    __shared__ float sh_c[NB][HID];
    __shared__ float sh_hd[NB][128];

    // ---- resident A fragments, gate-major permuted ----
    // Afr[mt][kt][0] = row gate(2mt)  unit u, col kt*8+tig
    // Afr[mt][kt][1] = row gate(2mt+1) unit u, col kt*8+tig
    // Afr[mt][kt][2] = gate(2mt)  col kt*8+tig+4
    // Afr[mt][kt][3] = gate(2mt+1) col kt*8+tig+4
    unsigned Afr[2][8][4];
    #pragma unroll
    for (int mt = 0; mt < 2; mt++) {
        const int rLo = (2 * mt) * HID + u;        // gate 2mt   row
        const int rHi = (2 * mt + 1) * HID + u;    // gate 2mt+1 row
        #pragma unroll
        for (int kt = 0; kt < 8; kt++) {
            Afr[mt][kt][0] = cvt_tf32(__ldg(W_hh + rLo * HID + kt * 8 + tig));
            Afr[mt][kt][1] = cvt_tf32(__ldg(W_hh + rHi * HID + kt * 8 + tig));
            Afr[mt][kt][2] = cvt_tf32(__ldg(W_hh + rLo * HID + kt * 8 + tig + 4));
            Afr[mt][kt][3] = cvt_tf32(__ldg(W_hh + rHi * HID + kt * 8 + tig + 4));
        }
    }
    // per-gate input weight + bias for unit u (gates 0..3)
    float wih[4], bias[4];
    #pragma unroll
    for (int g = 0; g < 4; g++) {
        const int r = g * HID + u;
        wih[g]  = __ldg(W_ih + r);
        bias[g] = __ldg(b_ih + r) + __ldg(b_hh + r);
    }

    float c0r = 0.0f, c1r = 0.0f;   // cell state, batches 2tig / 2tig+1
    int   p   = 0;

    // zero H buffer 0
    for (int idx = j; idx < HID * 8; idx += 256)
        sh_H[0][idx >> 3][idx & 7] = 0.0f;
    __syncthreads();

    // ---- time recurrence ----
    #pragma unroll 1
    for (int t0 = 0; t0 < SEQ; t0 += XCHUNK) {
        #pragma unroll
        for (int i = 0; i < (XCHUNK * NB) / 256; i++) {
            const int idx = j + i * 256;
            sh_x[idx] = __ldg(x + (t0 + (idx >> 3)) * BATCH + b0 + (idx & 7));
        }
        __syncthreads();

        #pragma unroll 1
        for (int tt = 0; tt < XCHUNK; tt++) {
            const float2 xv = *reinterpret_cast<const float2*>(&sh_x[tt * 8 + 2 * tig]);

            // accumulators: d[mt][0,1] = gate 2mt (b0,b1); d[mt][2,3] = gate 2mt+1
            // split K into two 4-deep partial chains (d, d2) for ILP
            float d [2][4];
            float d2[2][4];
            #pragma unroll
            for (int mt = 0; mt < 2; mt++) {
                d [mt][0] = fmaf(xv.x, wih[2 * mt],     bias[2 * mt]);
                d [mt][1] = fmaf(xv.y, wih[2 * mt],     bias[2 * mt]);
                d [mt][2] = fmaf(xv.x, wih[2 * mt + 1], bias[2 * mt + 1]);
                d [mt][3] = fmaf(xv.y, wih[2 * mt + 1], bias[2 * mt + 1]);
                d2[mt][0] = 0.0f; d2[mt][1] = 0.0f;
                d2[mt][2] = 0.0f; d2[mt][3] = 0.0f;
            }

            const float (*Hb)[8] = sh_H[p];
            #pragma unroll
            for (int kt = 0; kt < 4; kt++) {
                const unsigned bf0 = __float_as_uint(Hb[kt * 8 + tig][gid]);
                const unsigned bf1 = __float_as_uint(Hb[kt * 8 + tig + 4][gid]);
                mma_tf32(d[0][0], d[0][1], d[0][2], d[0][3],
                         Afr[0][kt][0], Afr[0][kt][1], Afr[0][kt][2], Afr[0][kt][3],
                         bf0, bf1);
                mma_tf32(d[1][0], d[1][1], d[1][2], d[1][3],
                         Afr[1][kt][0], Afr[1][kt][1], Afr[1][kt][2], Afr[1][kt][3],
                         bf0, bf1);
            }
            #pragma unroll
            for (int kt = 4; kt < 8; kt++) {
                const unsigned bf0 = __float_as_uint(Hb[kt * 8 + tig][gid]);
                const unsigned bf1 = __float_as_uint(Hb[kt * 8 + tig + 4][gid]);
                mma_tf32(d2[0][0], d2[0][1], d2[0][2], d2[0][3],
                         Afr[0][kt][0], Afr[0][kt][1], Afr[0][kt][2], Afr[0][kt][3],
                         bf0, bf1);
                mma_tf32(d2[1][0], d2[1][1], d2[1][2], d2[1][3],
                         Afr[1][kt][0], Afr[1][kt][1], Afr[1][kt][2], Afr[1][kt][3],
                         bf0, bf1);
            }

            // register-local LSTM update for unit u, batches 2tig / 2tig+1
            const float iv0 = sigA (d[0][0] + d2[0][0]);
            const float iv1 = sigA (d[0][1] + d2[0][1]);
            const float fv0 = sigA (d[0][2] + d2[0][2]);
            const float fv1 = sigA (d[0][3] + d2[0][3]);
            const float gv0 = tanhA(d[1][0] + d2[1][0]);
            const float gv1 = tanhA(d[1][1] + d2[1][1]);
            const float ov0 = sigA (d[1][2] + d2[1][2]);
            const float ov1 = sigA (d[1][3] + d2[1][3]);

            c0r = fmaf(fv0, c0r, iv0 * gv0);
            c1r = fmaf(fv1, c1r, iv1 * gv1);
            const float h0 = ov0 * tanhA(c0r);
            const float h1 = ov1 * tanhA(c1r);

            float2 hh;
            hh.x = __uint_as_float(cvt_tf32(h0));
            hh.y = __uint_as_float(cvt_tf32(h1));
            *reinterpret_cast<float2*>(&sh_H[p ^ 1][u][2 * tig]) = hh;
            __syncthreads();
            p ^= 1;
        }
    }

    // ---- MLP head on cell states (8 batches) ----
    sh_c[2 * tig][u]     = c0r;
    sh_c[2 * tig + 1][u] = c1r;
    __syncthreads();

    #pragma unroll
    for (int i = 0; i < 4; i++) {          // 8 batches x 128 rows = 1024 tasks
        const int t   = j + i * 256;
        const int row = t & 127;
        const int bt  = t >> 7;
        const float* fw = fc1_w + row * HID;
        float acc = __ldg(fc1_b + row);
        #pragma unroll
        for (int k = 0; k < HID; k++) acc = fmaf(__ldg(fw + k), sh_c[bt][k], acc);
        sh_hd[bt][row] = acc;
    }
    __syncthreads();

    if (j < NB * 5) {
        const int bt  = j / 5;
        const int row = j % 5;
        const float* fw = fc2_w + row * 128;
        float acc = __ldg(fc2_b + row);
        #pragma unroll
        for (int k = 0; k < 128; k++) acc = fmaf(__ldg(fw + k), sh_hd[bt][k], acc);
        out[(b0 + bt) * 5 + row] = acc;
    }
}

extern "C" void kernel_launch(void* const* d_in, const int* in_sizes, int n_in,
                              void* d_out, int out_size)
{
    const float* x     = (const float*)d_in[0];
    const float* W_ih  = (const float*)d_in[1];
    const float* W_hh  = (const float*)d_in[2];
    const float* b_ih  = (const float*)d_in[3];
    const float* b_hh  = (const float*)d_in[4];
    const float* fc1_w = (const float*)d_in[5];
    const float* fc1_b = (const float*)d_in[6];
    const float* fc2_w = (const float*)d_in[7];
    const float* fc2_b = (const float*)d_in[8];
    float* out = (float*)d_out;

    lstm_mma_kernel<<<BATCH / NB, 256>>>(x, W_ih, W_hh, b_ih, b_hh,
                                         fc1_w, fc1_b, fc2_w, fc2_b, out);
}